// round 12
// baseline (speedup 1.0000x reference)
#include <cuda_runtime.h>
#include <cstdint>

// VectorQuantizer: input (16, 64, 8192) fp32, codebook (1024, 64) fp32
// score(n,k) = 0.5*||e_k||^2 - x_n . e_k   (argmin-equivalent to ||x - e||^2)
//
// R12: tensor-core filter + exact rescore.
//   approx scores via mma.sync.m16n8k8 tf32, 3-term split (xh*eh + xh*el + xl*eh),
//   |approx - exact| <= EB. Per token keep top-2 approx, rescore exactly in fp32,
//   safety-check margin vs 2nd-best approx; rare violations -> full exact scan.

#define Dd 64
#define Kk 1024
#define Tt 8192
#define Nn (16 * 8192)
#define TPB 256
#define TOKS 128
#define NCHUNK 16
#define BCHUNK 16384             // one B-fragment image chunk (64 codes): 8nn*8kk*32*8B

#define AHI 0                    // A frags hi: 8m*8kk*32*16B = 32KB
#define ALO 32768                // A frags lo: 32KB
#define XPL 65536                // plain fp32 X: 128*64*4 = 32KB
#define BOFF0 98304              // B stage 0: hi 16KB | lo 16KB
#define BOFF1 (98304 + 32768)    // B stage 1
#define HOFFS (BOFF1 + 32768)    // 0.5||e||^2 : 4KB
#define SMEM_BYTES (HOFFS + 4096)  // 167936

#define EB 2e-3f

__device__ float g_half[Kk];
__device__ unsigned long long g_ebH[NCHUNK * 2048];   // B frag image, tf32 hi
__device__ unsigned long long g_ebL[NCHUNK * 2048];   // B frag image, tf32 lo

typedef unsigned long long u64;
typedef uint32_t u32;

__device__ __forceinline__ u32 f2tf(float x) {
    u32 r; asm("cvt.rna.tf32.f32 %0, %1;" : "=r"(r) : "f"(x)); return r;
}
__device__ __forceinline__ uint32_t s2u(const void* p) {
    uint32_t a;
    asm("{ .reg .u64 t; cvta.to.shared.u64 t, %1; cvt.u32.u64 %0, t; }" : "=r"(a) : "l"(p));
    return a;
}
__device__ __forceinline__ void cp16(uint32_t dst, const void* src) {
    uint64_t g = __cvta_generic_to_global(src);
    asm volatile("cp.async.cg.shared.global [%0], [%1], 16;" :: "r"(dst), "l"(g) : "memory");
}
__device__ __forceinline__ void cp_commit() { asm volatile("cp.async.commit_group;" ::: "memory"); }
template <int N>
__device__ __forceinline__ void cp_wait() { asm volatile("cp.async.wait_group %0;" :: "n"(N) : "memory"); }

__device__ __forceinline__ void mma8(float* d, const u32* a, u32 b0, u32 b1) {
    asm volatile(
        "mma.sync.aligned.m16n8k8.row.col.f32.tf32.tf32.f32 "
        "{%0,%1,%2,%3}, {%4,%5,%6,%7}, {%8,%9}, {%0,%1,%2,%3};"
        : "+f"(d[0]), "+f"(d[1]), "+f"(d[2]), "+f"(d[3])
        : "r"(a[0]), "r"(a[1]), "r"(a[2]), "r"(a[3]), "r"(b0), "r"(b1));
}

__device__ __forceinline__ void upd(float& s1, int& i1, float& s2, int& i2, float s, int i) {
    if (s < s1) { s2 = s1; i2 = i1; s1 = s; i1 = i; }
    else if (s < s2) { s2 = s; i2 = i; }
}

// merge partner top-2 into mine (smaller score wins; tie -> smaller index)
__device__ __forceinline__ void merge2(float& s1, int& i1, float& s2, int& i2, int off) {
    float t1 = __shfl_xor_sync(0xffffffffu, s1, off);
    float t2 = __shfl_xor_sync(0xffffffffu, s2, off);
    int   j1 = __shfl_xor_sync(0xffffffffu, i1, off);
    int   j2 = __shfl_xor_sync(0xffffffffu, i2, off);
    bool tf = (t1 < s1) || (t1 == s1 && j1 < i1);
    float n1 = tf ? t1 : s1;  int m1 = tf ? j1 : i1;
    float ca = tf ? s1 : t1;  int ia = tf ? i1 : j1;
    float cbv = tf ? t2 : s2; int ib = tf ? j2 : i2;
    bool af = (ca < cbv) || (ca == cbv && ia < ib);
    s1 = n1; i1 = m1;
    s2 = af ? ca : cbv; i2 = af ? ia : ib;
}

// ---- prologue: 0.5||e||^2 + tf32 hi/lo B-fragment images ----
__global__ void vq_pre(const float* __restrict__ cb) {
    int k = blockIdx.x * blockDim.x + threadIdx.x;
    if (k >= Kk) return;
    const float* row = cb + k * Dd;
    float s = 0.f;
#pragma unroll
    for (int d = 0; d < Dd; d++) s += row[d] * row[d];
    g_half[k] = 0.5f * s;
    int c = k >> 6, nn = (k >> 3) & 7, cq = k & 7;
#pragma unroll
    for (int kk = 0; kk < 8; kk++) {
#pragma unroll
        for (int rq = 0; rq < 4; rq++) {
            float e0 = row[kk * 8 + rq];
            float e1 = row[kk * 8 + rq + 4];
            u32 h0 = f2tf(e0), h1 = f2tf(e1);
            u32 l0 = f2tf(e0 - __uint_as_float(h0));
            u32 l1 = f2tf(e1 - __uint_as_float(h1));
            int idx = ((c * 8 + nn) * 8 + kk) * 32 + cq * 4 + rq;
            g_ebH[idx] = ((u64)h1 << 32) | h0;
            g_ebL[idx] = ((u64)l1 << 32) | l0;
        }
    }
}

__global__ __launch_bounds__(TPB, 1)
void vq_main(const float* __restrict__ input, const float* __restrict__ cb,
             float* __restrict__ out, float* __restrict__ out_idx) {
    extern __shared__ __align__(16) unsigned char smem[];
    const uint32_t sb = s2u(smem);
    const int tid = threadIdx.x, wid = tid >> 5, lane = tid & 31;
    const int tile = blockIdx.x, b = tile >> 6, tb = (tile & 63) * TOKS;

    // prefetch B chunk 0 (hi + lo)
#pragma unroll
    for (int s = 0; s < 4; s++) {
        int i = tid + s * TPB;
        cp16(sb + BOFF0 + i * 16, (const char*)g_ebH + i * 16);
        cp16(sb + BOFF0 + BCHUNK + i * 16, (const char*)g_ebL + i * 16);
    }
    cp_commit();

    // stage A frags (hi/lo) + plain X
    {
        const float* inb = input + (size_t)b * Dd * Tt + tb;
#pragma unroll 4
        for (int it = 0; it < 32; it++) {
            int idx = tid + it * TPB;
            int d = idx >> 7, t = idx & 127;
            float v = inb[(size_t)d * Tt + t];
            u32 h = f2tf(v);
            u32 l = f2tf(v - __uint_as_float(h));
            *(float*)(smem + XPL + (t * 64 + d) * 4) = v;
            int m = t >> 4, r = t & 15, kk = d >> 3, c4 = d & 7;
            int slot = (r >> 3) + ((c4 >> 2) << 1);
            int ln = ((r & 7) << 2) | (c4 & 3);
            u32 off = ((u32)(m * 8 + kk) * 32 + ln) * 16 + slot * 4;
            *(u32*)(smem + AHI + off) = h;
            *(u32*)(smem + ALO + off) = l;
        }
    }
    float* sH = (float*)(smem + HOFFS);
    for (int i = tid; i < Kk; i += TPB) sH[i] = g_half[i];
    __syncthreads();

    // A fragments to registers (this warp's 16-token m-tile)
    u32 ah[8][4], al[8][4];
#pragma unroll
    for (int kk = 0; kk < 8; kk++) {
        uint4 va = *(const uint4*)(smem + AHI + ((wid * 8 + kk) * 32 + lane) * 16);
        ah[kk][0] = va.x; ah[kk][1] = va.y; ah[kk][2] = va.z; ah[kk][3] = va.w;
        uint4 vb = *(const uint4*)(smem + ALO + ((wid * 8 + kk) * 32 + lane) * 16);
        al[kk][0] = vb.x; al[kk][1] = vb.y; al[kk][2] = vb.z; al[kk][3] = vb.w;
    }

    // top-2 approx per D-fragment row (row r = lane>>2 and r+8)
    float s1a = 3.4e38f, s2a = 3.4e38f, s1b = 3.4e38f, s2b = 3.4e38f;
    int   i1a = 0, i2a = 0, i1b = 0, i2b = 0;

    for (int c = 0; c < NCHUNK; c++) {
        const int st = c & 1;
        if (c + 1 < NCHUNK) {
            uint32_t nxt = sb + (st ? BOFF0 : BOFF1);
            const char* shp = (const char*)g_ebH + (size_t)(c + 1) * BCHUNK;
            const char* slp = (const char*)g_ebL + (size_t)(c + 1) * BCHUNK;
#pragma unroll
            for (int s = 0; s < 4; s++) {
                int i = tid + s * TPB;
                cp16(nxt + i * 16, shp + i * 16);
                cp16(nxt + BCHUNK + i * 16, slp + i * 16);
            }
            cp_commit();
            cp_wait<1>();
        } else {
            cp_wait<0>();
        }
        __syncthreads();

        const unsigned char* bhC = smem + (st ? BOFF1 : BOFF0);
        const unsigned char* blC = bhC + BCHUNK;

#pragma unroll
        for (int np = 0; np < 4; np++) {      // 2 interleaved n-tiles per pass
            float d0[4] = {0.f, 0.f, 0.f, 0.f}, d1[4] = {0.f, 0.f, 0.f, 0.f};
#pragma unroll
            for (int kk = 0; kk < 8; kk++) {
                u64 h0 = *(const u64*)(bhC + (((np * 2) * 8 + kk) * 32 + lane) * 8);
                u64 l0 = *(const u64*)(blC + (((np * 2) * 8 + kk) * 32 + lane) * 8);
                u64 h1 = *(const u64*)(bhC + (((np * 2 + 1) * 8 + kk) * 32 + lane) * 8);
                u64 l1 = *(const u64*)(blC + (((np * 2 + 1) * 8 + kk) * 32 + lane) * 8);
                mma8(d0, ah[kk], (u32)h0, (u32)(h0 >> 32));
                mma8(d1, ah[kk], (u32)h1, (u32)(h1 >> 32));
                mma8(d0, ah[kk], (u32)l0, (u32)(l0 >> 32));
                mma8(d1, ah[kk], (u32)l1, (u32)(l1 >> 32));
                mma8(d0, al[kk], (u32)h0, (u32)(h0 >> 32));
                mma8(d1, al[kk], (u32)h1, (u32)(h1 >> 32));
            }
            int cb0 = c * 64 + np * 16 + 2 * (lane & 3);
            float2 hp0 = *(const float2*)(sH + cb0);
            upd(s1a, i1a, s2a, i2a, hp0.x - d0[0], cb0);
            upd(s1a, i1a, s2a, i2a, hp0.y - d0[1], cb0 + 1);
            upd(s1b, i1b, s2b, i2b, hp0.x - d0[2], cb0);
            upd(s1b, i1b, s2b, i2b, hp0.y - d0[3], cb0 + 1);
            int cb1 = cb0 + 8;
            float2 hp1 = *(const float2*)(sH + cb1);
            upd(s1a, i1a, s2a, i2a, hp1.x - d1[0], cb1);
            upd(s1a, i1a, s2a, i2a, hp1.y - d1[1], cb1 + 1);
            upd(s1b, i1b, s2b, i2b, hp1.x - d1[2], cb1);
            upd(s1b, i1b, s2b, i2b, hp1.y - d1[3], cb1 + 1);
        }
        __syncthreads();
    }

    // merge across the 4 lanes sharing each row (cols are disjoint)
    merge2(s1a, i1a, s2a, i2a, 1); merge2(s1a, i1a, s2a, i2a, 2);
    merge2(s1b, i1b, s2b, i2b, 1); merge2(s1b, i1b, s2b, i2b, 2);

    // exact rescore: lane q=lane&3 handles (q<2 ? rowA : rowB), candidate (q&1)
    const int q = lane & 3;
    const int rbase = lane >> 2;
    const int myrow = (q < 2) ? rbase : rbase + 8;
    const int cand = (q == 0) ? i1a : (q == 1) ? i2a : (q == 2) ? i1b : i2b;
    const float s2app = (q < 2) ? s2a : s2b;
    const int tloc = wid * 16 + myrow;
    const float4* xr = (const float4*)(smem + XPL + tloc * 256);

    float sex;
    {
        const float4* er = (const float4*)(cb + (size_t)cand * 64);
        float a0 = 0.f, a1 = 0.f, a2 = 0.f, a3 = 0.f;
#pragma unroll
        for (int i = 0; i < 16; i += 4) {
            float4 xv, ev;
            xv = xr[i];     ev = er[i];     a0 = fmaf(xv.x, ev.x, fmaf(xv.y, ev.y, fmaf(xv.z, ev.z, fmaf(xv.w, ev.w, a0))));
            xv = xr[i + 1]; ev = er[i + 1]; a1 = fmaf(xv.x, ev.x, fmaf(xv.y, ev.y, fmaf(xv.z, ev.z, fmaf(xv.w, ev.w, a1))));
            xv = xr[i + 2]; ev = er[i + 2]; a2 = fmaf(xv.x, ev.x, fmaf(xv.y, ev.y, fmaf(xv.z, ev.z, fmaf(xv.w, ev.w, a2))));
            xv = xr[i + 3]; ev = er[i + 3]; a3 = fmaf(xv.x, ev.x, fmaf(xv.y, ev.y, fmaf(xv.z, ev.z, fmaf(xv.w, ev.w, a3))));
        }
        sex = sH[cand] - ((a0 + a1) + (a2 + a3));
    }
    float po = __shfl_xor_sync(0xffffffffu, sex, 1);
    int   pc = __shfl_xor_sync(0xffffffffu, cand, 1);

    if ((q & 1) == 0) {
        bool mine = (sex < po) || (sex == po && cand < pc);
        int ichosen = mine ? cand : pc;
        float schosen = mine ? sex : po;
        if (!(schosen < s2app - EB)) {
            // rare: margin violated -> exact full scan (first-occurrence argmin)
            float bsf = 3.4e38f; int bif = 0;
            for (int k2 = 0; k2 < Kk; k2++) {
                const float4* e2 = (const float4*)(cb + (size_t)k2 * 64);
                float a0 = 0.f, a1 = 0.f, a2 = 0.f, a3 = 0.f;
#pragma unroll 4
                for (int i = 0; i < 16; i += 4) {
                    float4 xv, ev;
                    xv = xr[i];     ev = e2[i];     a0 = fmaf(xv.x, ev.x, fmaf(xv.y, ev.y, fmaf(xv.z, ev.z, fmaf(xv.w, ev.w, a0))));
                    xv = xr[i + 1]; ev = e2[i + 1]; a1 = fmaf(xv.x, ev.x, fmaf(xv.y, ev.y, fmaf(xv.z, ev.z, fmaf(xv.w, ev.w, a1))));
                    xv = xr[i + 2]; ev = e2[i + 2]; a2 = fmaf(xv.x, ev.x, fmaf(xv.y, ev.y, fmaf(xv.z, ev.z, fmaf(xv.w, ev.w, a2))));
                    xv = xr[i + 3]; ev = e2[i + 3]; a3 = fmaf(xv.x, ev.x, fmaf(xv.y, ev.y, fmaf(xv.z, ev.z, fmaf(xv.w, ev.w, a3))));
                }
                float ss = sH[k2] - ((a0 + a1) + (a2 + a3));
                if (ss < bsf) { bsf = ss; bif = k2; }
            }
            ichosen = bif;
        }
        // write output for token tloc
        const int tglob = tb + tloc;
        float* ob = out + (size_t)b * Dd * Tt + tglob;
        const float4* cv = (const float4*)(cb + (size_t)ichosen * 64);
#pragma unroll
        for (int i = 0; i < 16; i++) {
            float4 v = cv[i];
            ob[(size_t)(4 * i + 0) * Tt] = v.x;
            ob[(size_t)(4 * i + 1) * Tt] = v.y;
            ob[(size_t)(4 * i + 2) * Tt] = v.z;
            ob[(size_t)(4 * i + 3) * Tt] = v.w;
        }
        if (out_idx != nullptr) out_idx[(size_t)b * Tt + tglob] = (float)ichosen;
    }
}

extern "C" void kernel_launch(void* const* d_in, const int* in_sizes, int n_in,
                              void* d_out, int out_size) {
    const float* input = (const float*)d_in[0];   // (16, 64, 8192) fp32
    const float* cb    = (const float*)d_in[1];   // (1024, 64) fp32
    float* out = (float*)d_out;

    float* out_idx = nullptr;
    if (out_size >= (int)((long)Nn * Dd + Nn)) out_idx = out + (long)Nn * Dd;

    cudaFuncSetAttribute(vq_main, cudaFuncAttributeMaxDynamicSharedMemorySize, SMEM_BYTES);

    vq_pre<<<(Kk + 127) / 128, 128>>>(cb);
    vq_main<<<Nn / TOKS, TPB, SMEM_BYTES>>>(input, cb, out, out_idx);
}

// round 13
// speedup vs baseline: 1.1012x; 1.1012x over previous
#include <cuda_runtime.h>
#include <cstdint>

// VectorQuantizer: input (16, 64, 8192) fp32, codebook (1024, 64) fp32
// score(n,k) = 0.5*||e_k||^2 - x_n . e_k   (argmin-equivalent to ||x - e||^2)
//
// R13: tensor-core filter (mma.sync m16n8k8 tf32, 3-term split) + exact fp32
// rescore of per-token top-2 (R12-verified). Restructured: 8 concurrent
// D-chains per warp, A-frags rebuilt per-kk from padded plain-X smem
// (no persistent A regs, no A staging) -> 2 CTAs/SM, 16 warps.

#define Dd 64
#define Kk 1024
#define Tt 8192
#define Nn (16 * 8192)
#define TPB 256
#define TOKS 128
#define NCHUNK 16
#define BCHUNK 16384             // 64 codes: 8n*8kk*32lanes*8B

#define XSTRIDE 68               // floats per token row (64 + 4 pad): conflict-free frag gather
#define XOFF 0
#define XBYTES (TOKS * XSTRIDE * 4)      // 34816
#define BOFF0 XBYTES
#define BOFF1 (BOFF0 + 2 * BCHUNK)       // 67584
#define HOFFS (BOFF1 + 2 * BCHUNK)       // 100352
#define SMEM_BYTES (HOFFS + 4096)        // 104448

#define EB 2e-3f

__device__ float g_half[Kk];
__device__ unsigned long long g_ebH[NCHUNK * 2048];   // B frag image, tf32 hi
__device__ unsigned long long g_ebL[NCHUNK * 2048];   // B frag image, tf32 lo

typedef unsigned long long u64;
typedef uint32_t u32;

__device__ __forceinline__ u32 f2tf(float x) {
    u32 r; asm("cvt.rna.tf32.f32 %0, %1;" : "=r"(r) : "f"(x)); return r;
}
__device__ __forceinline__ uint32_t s2u(const void* p) {
    uint32_t a;
    asm("{ .reg .u64 t; cvta.to.shared.u64 t, %1; cvt.u32.u64 %0, t; }" : "=r"(a) : "l"(p));
    return a;
}
__device__ __forceinline__ void cp16(uint32_t dst, const void* src) {
    uint64_t g = __cvta_generic_to_global(src);
    asm volatile("cp.async.cg.shared.global [%0], [%1], 16;" :: "r"(dst), "l"(g) : "memory");
}
__device__ __forceinline__ void cp_commit() { asm volatile("cp.async.commit_group;" ::: "memory"); }
template <int N>
__device__ __forceinline__ void cp_wait() { asm volatile("cp.async.wait_group %0;" :: "n"(N) : "memory"); }

__device__ __forceinline__ void mma8(float* d, const u32* a, u32 b0, u32 b1) {
    asm volatile(
        "mma.sync.aligned.m16n8k8.row.col.f32.tf32.tf32.f32 "
        "{%0,%1,%2,%3}, {%4,%5,%6,%7}, {%8,%9}, {%0,%1,%2,%3};"
        : "+f"(d[0]), "+f"(d[1]), "+f"(d[2]), "+f"(d[3])
        : "r"(a[0]), "r"(a[1]), "r"(a[2]), "r"(a[3]), "r"(b0), "r"(b1));
}

__device__ __forceinline__ void upd(float& s1, int& i1, float& s2, int& i2, float s, int i) {
    if (s < s1) { s2 = s1; i2 = i1; s1 = s; i1 = i; }
    else if (s < s2) { s2 = s; i2 = i; }
}
__device__ __forceinline__ void merge2(float& s1, int& i1, float& s2, int& i2, int off) {
    float t1 = __shfl_xor_sync(0xffffffffu, s1, off);
    float t2 = __shfl_xor_sync(0xffffffffu, s2, off);
    int   j1 = __shfl_xor_sync(0xffffffffu, i1, off);
    int   j2 = __shfl_xor_sync(0xffffffffu, i2, off);
    bool tf = (t1 < s1) || (t1 == s1 && j1 < i1);
    float n1 = tf ? t1 : s1;  int m1 = tf ? j1 : i1;
    float ca = tf ? s1 : t1;  int ia = tf ? i1 : j1;
    float cbv = tf ? t2 : s2; int ib = tf ? j2 : i2;
    bool af = (ca < cbv) || (ca == cbv && ia < ib);
    s1 = n1; i1 = m1;
    s2 = af ? ca : cbv; i2 = af ? ia : ib;
}

// ---- prologue: 0.5||e||^2 + tf32 hi/lo B-fragment images (R12-verified) ----
__global__ void vq_pre(const float* __restrict__ cb) {
    int k = blockIdx.x * blockDim.x + threadIdx.x;
    if (k >= Kk) return;
    const float* row = cb + k * Dd;
    float s = 0.f;
#pragma unroll
    for (int d = 0; d < Dd; d++) s += row[d] * row[d];
    g_half[k] = 0.5f * s;
    int c = k >> 6, nn = (k >> 3) & 7, cq = k & 7;
#pragma unroll
    for (int kk = 0; kk < 8; kk++) {
#pragma unroll
        for (int rq = 0; rq < 4; rq++) {
            float e0 = row[kk * 8 + rq];
            float e1 = row[kk * 8 + rq + 4];
            u32 h0 = f2tf(e0), h1 = f2tf(e1);
            u32 l0 = f2tf(e0 - __uint_as_float(h0));
            u32 l1 = f2tf(e1 - __uint_as_float(h1));
            int idx = ((c * 8 + nn) * 8 + kk) * 32 + cq * 4 + rq;
            g_ebH[idx] = ((u64)h1 << 32) | h0;
            g_ebL[idx] = ((u64)l1 << 32) | l0;
        }
    }
}

__global__ __launch_bounds__(TPB, 2)
void vq_main(const float* __restrict__ input, const float* __restrict__ cb,
             float* __restrict__ out, float* __restrict__ out_idx) {
    extern __shared__ __align__(16) unsigned char smem[];
    const uint32_t sb = s2u(smem);
    const int tid = threadIdx.x, wid = tid >> 5, lane = tid & 31;
    const int r4 = lane >> 2, c4b = lane & 3;
    const int tile = blockIdx.x, b = tile >> 6, tb = (tile & 63) * TOKS;

    float* Xs = (float*)(smem + XOFF);
    float* sH = (float*)(smem + HOFFS);

    // prefetch B chunk 0 (hi + lo)
#pragma unroll
    for (int s = 0; s < 4; s++) {
        int i = tid + s * TPB;
        cp16(sb + BOFF0 + i * 16, (const char*)g_ebH + i * 16);
        cp16(sb + BOFF0 + BCHUNK + i * 16, (const char*)g_ebL + i * 16);
    }
    cp_commit();

    // stage plain X (padded rows), coalesced global reads
    {
        const float* inb = input + (size_t)b * Dd * Tt + tb;
#pragma unroll 8
        for (int it = 0; it < 32; it++) {
            int idx = tid + it * TPB;
            int d = idx >> 7, t = idx & 127;
            Xs[t * XSTRIDE + d] = inb[(size_t)d * Tt + t];
        }
    }
    for (int i = tid; i < Kk; i += TPB) sH[i] = g_half[i];

    // top-2 approx per D-fragment row pair (rows r4 and r4+8 of this warp's m-tile)
    float s1a = 3.4e38f, s2a = 3.4e38f, s1b = 3.4e38f, s2b = 3.4e38f;
    int   i1a = 0, i2a = 0, i1b = 0, i2b = 0;

    const float* Xfrag0 = Xs + (wid * 16 + r4) * XSTRIDE + c4b;   // row r4
    const float* Xfrag1 = Xfrag0 + 8 * XSTRIDE;                   // row r4+8

    for (int c = 0; c < NCHUNK; c++) {
        const int st = c & 1;
        if (c + 1 < NCHUNK) {
            uint32_t nxt = sb + (st ? BOFF0 : BOFF1);
            const char* shp = (const char*)g_ebH + (size_t)(c + 1) * BCHUNK;
            const char* slp = (const char*)g_ebL + (size_t)(c + 1) * BCHUNK;
#pragma unroll
            for (int s = 0; s < 4; s++) {
                int i = tid + s * TPB;
                cp16(nxt + i * 16, shp + i * 16);
                cp16(nxt + BCHUNK + i * 16, slp + i * 16);
            }
            cp_commit();
            cp_wait<1>();
        } else {
            cp_wait<0>();
        }
        __syncthreads();

        const unsigned char* bhC = smem + (st ? BOFF1 : BOFF0);
        const unsigned char* blC = bhC + BCHUNK;

        float d[8][4];
#pragma unroll
        for (int n = 0; n < 8; n++)
#pragma unroll
            for (int j = 0; j < 4; j++) d[n][j] = 0.f;

#pragma unroll
        for (int kk = 0; kk < 8; kk++) {
            // rebuild A fragment (hi/lo) for this kk from plain X
            float xa0 = Xfrag0[kk * 8];          // (r4,      c4b)
            float xa1 = Xfrag1[kk * 8];          // (r4+8,    c4b)
            float xa2 = Xfrag0[kk * 8 + 4];      // (r4,      c4b+4)
            float xa3 = Xfrag1[kk * 8 + 4];      // (r4+8,    c4b+4)
            u32 ah[4], al[4];
            ah[0] = f2tf(xa0); al[0] = f2tf(xa0 - __uint_as_float(ah[0]));
            ah[1] = f2tf(xa1); al[1] = f2tf(xa1 - __uint_as_float(ah[1]));
            ah[2] = f2tf(xa2); al[2] = f2tf(xa2 - __uint_as_float(ah[2]));
            ah[3] = f2tf(xa3); al[3] = f2tf(xa3 - __uint_as_float(ah[3]));
#pragma unroll
            for (int n = 0; n < 8; n++) {        // 8 independent D chains
                u64 h = *(const u64*)(bhC + (u32)(((n * 8 + kk) * 32 + lane) * 8));
                u64 l = *(const u64*)(blC + (u32)(((n * 8 + kk) * 32 + lane) * 8));
                mma8(d[n], ah, (u32)h, (u32)(h >> 32));
                mma8(d[n], al, (u32)h, (u32)(h >> 32));
                mma8(d[n], ah, (u32)l, (u32)(l >> 32));
            }
        }

        // fold tile scores into per-row top-2
#pragma unroll
        for (int n = 0; n < 8; n++) {
            int cb0 = c * 64 + n * 8 + 2 * c4b;
            float2 hp = *(const float2*)(sH + cb0);
            upd(s1a, i1a, s2a, i2a, hp.x - d[n][0], cb0);
            upd(s1a, i1a, s2a, i2a, hp.y - d[n][1], cb0 + 1);
            upd(s1b, i1b, s2b, i2b, hp.x - d[n][2], cb0);
            upd(s1b, i1b, s2b, i2b, hp.y - d[n][3], cb0 + 1);
        }
        __syncthreads();
    }

    // merge across the 4 lanes sharing each row
    merge2(s1a, i1a, s2a, i2a, 1); merge2(s1a, i1a, s2a, i2a, 2);
    merge2(s1b, i1b, s2b, i2b, 1); merge2(s1b, i1b, s2b, i2b, 2);

    // exact rescore: lane q handles (q<2 ? rowA : rowB), candidate (q&1)
    const int q = c4b;
    const int myrow = (q < 2) ? r4 : r4 + 8;
    const int cand = (q == 0) ? i1a : (q == 1) ? i2a : (q == 2) ? i1b : i2b;
    const float s2app = (q < 2) ? s2a : s2b;
    const int tloc = wid * 16 + myrow;
    const float4* xr = (const float4*)(Xs + tloc * XSTRIDE);

    float sex;
    {
        const float4* er = (const float4*)(cb + (size_t)cand * 64);
        float a0 = 0.f, a1 = 0.f, a2 = 0.f, a3 = 0.f;
#pragma unroll
        for (int i = 0; i < 16; i += 4) {
            float4 xv, ev;
            xv = xr[i];     ev = er[i];     a0 = fmaf(xv.x, ev.x, fmaf(xv.y, ev.y, fmaf(xv.z, ev.z, fmaf(xv.w, ev.w, a0))));
            xv = xr[i + 1]; ev = er[i + 1]; a1 = fmaf(xv.x, ev.x, fmaf(xv.y, ev.y, fmaf(xv.z, ev.z, fmaf(xv.w, ev.w, a1))));
            xv = xr[i + 2]; ev = er[i + 2]; a2 = fmaf(xv.x, ev.x, fmaf(xv.y, ev.y, fmaf(xv.z, ev.z, fmaf(xv.w, ev.w, a2))));
            xv = xr[i + 3]; ev = er[i + 3]; a3 = fmaf(xv.x, ev.x, fmaf(xv.y, ev.y, fmaf(xv.z, ev.z, fmaf(xv.w, ev.w, a3))));
        }
        sex = sH[cand] - ((a0 + a1) + (a2 + a3));
    }
    float po = __shfl_xor_sync(0xffffffffu, sex, 1);
    int   pc = __shfl_xor_sync(0xffffffffu, cand, 1);

    if ((q & 1) == 0) {
        bool mine = (sex < po) || (sex == po && cand < pc);
        int ichosen = mine ? cand : pc;
        float schosen = mine ? sex : po;
        if (!(schosen < s2app - EB)) {
            // rare: margin violated -> exact full scan (first-occurrence argmin)
            float bsf = 3.4e38f; int bif = 0;
            for (int k2 = 0; k2 < Kk; k2++) {
                const float4* e2 = (const float4*)(cb + (size_t)k2 * 64);
                float a0 = 0.f, a1 = 0.f, a2 = 0.f, a3 = 0.f;
#pragma unroll 4
                for (int i = 0; i < 16; i += 4) {
                    float4 xv, ev;
                    xv = xr[i];     ev = e2[i];     a0 = fmaf(xv.x, ev.x, fmaf(xv.y, ev.y, fmaf(xv.z, ev.z, fmaf(xv.w, ev.w, a0))));
                    xv = xr[i + 1]; ev = e2[i + 1]; a1 = fmaf(xv.x, ev.x, fmaf(xv.y, ev.y, fmaf(xv.z, ev.z, fmaf(xv.w, ev.w, a1))));
                    xv = xr[i + 2]; ev = e2[i + 2]; a2 = fmaf(xv.x, ev.x, fmaf(xv.y, ev.y, fmaf(xv.z, ev.z, fmaf(xv.w, ev.w, a2))));
                    xv = xr[i + 3]; ev = e2[i + 3]; a3 = fmaf(xv.x, ev.x, fmaf(xv.y, ev.y, fmaf(xv.z, ev.z, fmaf(xv.w, ev.w, a3))));
                }
                float ss = sH[k2] - ((a0 + a1) + (a2 + a3));
                if (ss < bsf) { bsf = ss; bif = k2; }
            }
            ichosen = bif;
        }
        const int tglob = tb + tloc;
        float* ob = out + (size_t)b * Dd * Tt + tglob;
        const float4* cv = (const float4*)(cb + (size_t)ichosen * 64);
#pragma unroll
        for (int i = 0; i < 16; i++) {
            float4 v = cv[i];
            ob[(size_t)(4 * i + 0) * Tt] = v.x;
            ob[(size_t)(4 * i + 1) * Tt] = v.y;
            ob[(size_t)(4 * i + 2) * Tt] = v.z;
            ob[(size_t)(4 * i + 3) * Tt] = v.w;
        }
        if (out_idx != nullptr) out_idx[(size_t)b * Tt + tglob] = (float)ichosen;
    }
}

extern "C" void kernel_launch(void* const* d_in, const int* in_sizes, int n_in,
                              void* d_out, int out_size) {
    const float* input = (const float*)d_in[0];   // (16, 64, 8192) fp32
    const float* cb    = (const float*)d_in[1];   // (1024, 64) fp32
    float* out = (float*)d_out;

    float* out_idx = nullptr;
    if (out_size >= (int)((long)Nn * Dd + Nn)) out_idx = out + (long)Nn * Dd;

    cudaFuncSetAttribute(vq_main, cudaFuncAttributeMaxDynamicSharedMemorySize, SMEM_BYTES);

    vq_pre<<<(Kk + 127) / 128, 128>>>(cb);
    vq_main<<<Nn / TOKS, TPB, SMEM_BYTES>>>(input, cb, out, out_idx);
}